// round 12
// baseline (speedup 1.0000x reference)
#include <cuda_runtime.h>
#include <math.h>

#define NB    32     // batch
#define LSEQ  1024
#define CH    34
#define D     256
#define NE    8
#define NP    4      // only first 4 patches survive the [:, :seq_len] slice
#define PL    16
#define PRED  96

// Scratch (device globals — no allocation allowed).
__device__ float g_red[NB][8][2];             // per-segment partial sums
__device__ __align__(16) float g_partial[NB][NE][NP * D];

// ---------------------------------------------------------------------------
// cp.async helpers (LDGSTS) + packed f32x2 FMA (sm_103a)
// ---------------------------------------------------------------------------
__device__ __forceinline__ void cp16(void* dst_smem, const void* src) {
    unsigned saddr = (unsigned)__cvta_generic_to_shared(dst_smem);
    asm volatile("cp.async.cg.shared.global [%0], [%1], 16;\n"
                 :: "r"(saddr), "l"(src));
}
#define CP_COMMIT()  asm volatile("cp.async.commit_group;\n" ::: "memory")
#define CP_WAIT(n)   asm volatile("cp.async.wait_group %0;\n" :: "n"(n) : "memory")

#define FMA2(acc, a, b) \
    asm("fma.rn.f32x2 %0, %1, %2, %0;" : "+l"(acc) : "l"(a), "l"(b))

__device__ __forceinline__ float f32x2_hsum(unsigned long long v) {
    unsigned lo, hi;
    asm("mov.b64 {%0, %1}, %2;" : "=r"(lo), "=r"(hi) : "l"(v));
    return __uint_as_float(lo) + __uint_as_float(hi);
}

// ---------------------------------------------------------------------------
// K0: wide partial stats over x[b,:,2].  grid = 256 blocks (b*8+seg), 128 thr.
// ---------------------------------------------------------------------------
__global__ void __launch_bounds__(128)
k0_stats(const float* __restrict__ x) {
    const int blk = blockIdx.x;
    const int b   = blk >> 3;
    const int seg = blk & 7;
    const int tid  = threadIdx.x;
    const int warp = tid >> 5;
    const int lane = tid & 31;

    __shared__ float sred[8];

    const float v = x[(size_t)b * LSEQ * CH + (size_t)(seg * 128 + tid) * CH + 2];

    float sum = v, sq = v * v;
    #pragma unroll
    for (int o = 16; o; o >>= 1) {
        sum += __shfl_xor_sync(0xffffffffu, sum, o);
        sq  += __shfl_xor_sync(0xffffffffu, sq,  o);
    }
    if (lane == 0) { sred[warp] = sum; sred[4 + warp] = sq; }
    __syncthreads();
    if (tid == 0) {
        g_red[b][seg][0] = (sred[0] + sred[1]) + (sred[2] + sred[3]);
        g_red[b][seg][1] = (sred[4] + sred[5]) + (sred[6] + sred[7]);
    }
}

// ---------------------------------------------------------------------------
// K2: fused prologue (stats-finalize + xp + router) + per-expert smem GEMM.
// grid = (8 e, 4 b-tiles, 4 h-tiles), 256 threads.  warp w owns b = bt*8+w.
// ---------------------------------------------------------------------------
#define K2_SMEM_BYTES (8258 * 16)

__global__ void __launch_bounds__(256)
k2_fused(const float* __restrict__ x,
         const float* __restrict__ W_proj,
         const float* __restrict__ b_proj,
         const float* __restrict__ W_router,
         const float* __restrict__ b_router,
         const float* __restrict__ W_experts,
         const float* __restrict__ b_experts) {
    extern __shared__ float4 smem4[];
    float4* s_w   = smem4;                 // 64*65  W tile
    float4* s_xp  = smem4 + 4160;          // 32*65  xp rows
    float4* s_wp  = smem4 + 6240;          // 256*5  W_proj padded
    float4* s_wr  = smem4 + 7520;          // 8*65   W_router padded
    float4* s_be4 = smem4 + 8040;          // 16     b_experts slice
    float4* s_br4 = smem4 + 8056;          // 2      b_router
    float4* s_bp4 = smem4 + 8058;          // 64     b_proj
    float*  s_xn  = (float*)(smem4 + 8122);
    float*  s_g   = s_xn + 512;
    float*  s_xpf = (float*)s_xp;
    const float* s_bef = (const float*)s_be4;
    const float* s_brf = (const float*)s_br4;
    const float* s_bpf = (const float*)s_bp4;

    const int e   = blockIdx.x;
    const int bt  = blockIdx.y;
    const int htb = blockIdx.z;
    const int tid  = threadIdx.x;
    const int warp = tid >> 5;
    const int lane = tid & 31;
    const int b    = bt * 8 + warp;

    // ---- plain loads first (x values + stats partials) ----
    const float v0 = x[(size_t)b * LSEQ * CH + (size_t)lane * CH + 2];
    const float v1 = x[(size_t)b * LSEQ * CH + (size_t)(lane + 32) * CH + 2];
    float rs = 0.f, rq = 0.f;
    if (lane < 8) { rs = g_red[b][lane][0]; rq = g_red[b][lane][1]; }

    // ---- cp.async group0: small weights ----
    const float4* Wp4 = reinterpret_cast<const float4*>(W_proj);
    #pragma unroll
    for (int i = 0; i < 4; i++) {
        const int g = tid + 256 * i;
        cp16(&s_wp[(g >> 2) * 5 + (g & 3)], &Wp4[g]);
    }
    const float4* Wr4 = reinterpret_cast<const float4*>(W_router);
    #pragma unroll
    for (int i = 0; i < 2; i++) {
        const int g = tid + 256 * i;
        cp16(&s_wr[(g >> 6) * 65 + (g & 63)], &Wr4[g]);
    }
    if (tid < 16) cp16(&s_be4[tid],
                       reinterpret_cast<const float4*>(b_experts + e * D + htb * 64) + tid);
    if (tid < 2)  cp16(&s_br4[tid], reinterpret_cast<const float4*>(b_router) + tid);
    if (tid < 64) cp16(&s_bp4[tid], reinterpret_cast<const float4*>(b_proj) + tid);
    CP_COMMIT();

    // ---- cp.async group1: the big W tile ----
    const float4* Wg = reinterpret_cast<const float4*>(W_experts);
    #pragma unroll
    for (int r = 0; r < 16; r++) {
        const int flat = r * 256 + tid;
        const int row = flat >> 6, col = flat & 63;
        cp16(&s_w[row * 65 + col], &Wg[(size_t)(e * D + htb * 64 + row) * 64 + col]);
    }
    CP_COMMIT();

    // ---- finalize stats (per-warp, 8-lane shfl tree) ----
    #pragma unroll
    for (int o = 4; o; o >>= 1) {
        rs += __shfl_xor_sync(0xffffffffu, rs, o, 8);
        rq += __shfl_xor_sync(0xffffffffu, rq, o, 8);
    }
    rs = __shfl_sync(0xffffffffu, rs, 0);
    rq = __shfl_sync(0xffffffffu, rq, 0);
    const float mean = rs * (1.0f / LSEQ);
    const float var  = rq * (1.0f / LSEQ) - mean * mean;
    const float inv  = 1.0f / sqrtf(var + 1e-5f);

    s_xn[warp * 64 + lane]      = (v0 - mean) * inv;
    s_xn[warp * 64 + lane + 32] = (v1 - mean) * inv;

    CP_WAIT(1);          // group0 (small weights) complete on this thread
    __syncthreads();     // ... and on all threads; s_xn also visible

    // ---- xp: lane computes d = lane + 32*dd for its warp's b ----
    const float* xnw = s_xn + warp * 64;
    #pragma unroll
    for (int dd = 0; dd < 8; dd++) {
        const int d = lane + dd * 32;
        float w[PL];
        #pragma unroll
        for (int q = 0; q < 4; q++) {
            const float4 t = s_wp[d * 5 + q];
            w[q * 4 + 0] = t.x; w[q * 4 + 1] = t.y;
            w[q * 4 + 2] = t.z; w[q * 4 + 3] = t.w;
        }
        const float bp = s_bpf[d];
        #pragma unroll
        for (int p = 0; p < NP; p++) {
            float acc = bp;
            #pragma unroll
            for (int k = 0; k < PL; k++) acc = fmaf(w[k], xnw[p * PL + k], acc);
            s_xpf[(warp * 4 + p) * 260 + d] = acc;
        }
    }
    __syncwarp();

    // ---- router: lane = (p, chunk); xp chunk in regs, W broadcast loads ----
    {
        const int c = lane & 7;             // 32-d chunk
        const int p = lane >> 3;
        const float4* xch = s_xp + (warp * 4 + p) * 65 + c * 8;
        float4 xr[8];
        #pragma unroll
        for (int j = 0; j < 8; j++) xr[j] = xch[j];

        float logit[NE];
        #pragma unroll
        for (int ee = 0; ee < NE; ee++) {
            const float4* wch = s_wr + ee * 65 + c * 8;   // same addr for 4 lanes
            float a = 0.f;
            #pragma unroll
            for (int j = 0; j < 8; j++) {
                const float4 w = wch[j];
                a = fmaf(w.x, xr[j].x, a); a = fmaf(w.y, xr[j].y, a);
                a = fmaf(w.z, xr[j].z, a); a = fmaf(w.w, xr[j].w, a);
            }
            logit[ee] = a;
        }
        #pragma unroll
        for (int o = 4; o; o >>= 1)
            #pragma unroll
            for (int ee = 0; ee < NE; ee++)
                logit[ee] += __shfl_xor_sync(0xffffffffu, logit[ee], o, 8);

        #pragma unroll
        for (int ee = 0; ee < NE; ee++) logit[ee] += s_brf[ee];
        float m = logit[0];
        #pragma unroll
        for (int ee = 1; ee < NE; ee++) m = fmaxf(m, logit[ee]);
        float den = 0.f;
        #pragma unroll
        for (int ee = 0; ee < NE; ee++) den += __expf(logit[ee] - m);
        if (c == 0) s_g[warp * 4 + p] = __expf(logit[e] - m) / den;
    }

    CP_WAIT(0);          // W tile resident
    __syncthreads();

    // ---- GEMM (packed f32x2): thread = (rt row-tile, ht strided-h, kh) ----
    const int kh = tid & 1;
    const int ht = (tid >> 1) & 15;
    const int rt = tid >> 5;

    unsigned long long acc[4][4];
    #pragma unroll
    for (int i = 0; i < 4; i++)
        #pragma unroll
        for (int j = 0; j < 4; j++) acc[i][j] = 0ULL;

    const float4* xb4 = s_xp + rt * 4 * 65 + kh * 32;
    const float4* wb4 = s_w  + ht * 65     + kh * 32;

    #pragma unroll 4
    for (int kk = 0; kk < 32; kk++) {
        const ulonglong2 x0 = *reinterpret_cast<const ulonglong2*>(&xb4[0 * 65 + kk]);
        const ulonglong2 x1 = *reinterpret_cast<const ulonglong2*>(&xb4[1 * 65 + kk]);
        const ulonglong2 x2 = *reinterpret_cast<const ulonglong2*>(&xb4[2 * 65 + kk]);
        const ulonglong2 x3 = *reinterpret_cast<const ulonglong2*>(&xb4[3 * 65 + kk]);
        const ulonglong2 w0 = *reinterpret_cast<const ulonglong2*>(&wb4[0 * 1040 + kk]);
        const ulonglong2 w1 = *reinterpret_cast<const ulonglong2*>(&wb4[1 * 1040 + kk]);
        const ulonglong2 w2 = *reinterpret_cast<const ulonglong2*>(&wb4[2 * 1040 + kk]);
        const ulonglong2 w3 = *reinterpret_cast<const ulonglong2*>(&wb4[3 * 1040 + kk]);
        #pragma unroll
        for (int i = 0; i < 4; i++) {
            const ulonglong2 xv = (i == 0) ? x0 : (i == 1) ? x1 : (i == 2) ? x2 : x3;
            FMA2(acc[i][0], xv.x, w0.x); FMA2(acc[i][0], xv.y, w0.y);
            FMA2(acc[i][1], xv.x, w1.x); FMA2(acc[i][1], xv.y, w1.y);
            FMA2(acc[i][2], xv.x, w2.x); FMA2(acc[i][2], xv.y, w2.y);
            FMA2(acc[i][3], xv.x, w3.x); FMA2(acc[i][3], xv.y, w3.y);
        }
    }

    float accs[4][4];
    #pragma unroll
    for (int i = 0; i < 4; i++)
        #pragma unroll
        for (int j = 0; j < 4; j++) {
            float s = f32x2_hsum(acc[i][j]);
            s += __shfl_xor_sync(0xffffffffu, s, 1);
            accs[i][j] = s;
        }

    if (kh == 0) {
        #pragma unroll
        for (int i = 0; i < 4; i++) {
            const int r  = rt * 4 + i;
            const int bb = bt * 8 + (r >> 2);
            const int p  = r & 3;
            const float g = s_g[r];
            #pragma unroll
            for (int j = 0; j < 4; j++) {
                const int hl = ht + j * 16;
                g_partial[bb][e][p * D + htb * 64 + hl] = g * (accs[i][j] + s_bef[hl]);
            }
        }
    }
}

// ---------------------------------------------------------------------------
// K3: combine 8 experts + de-normalize + head matvec.
// grid = (32 b, 12 t-tiles), 256 threads; 8 warps -> 8 outputs per block.
// ---------------------------------------------------------------------------
__global__ void __launch_bounds__(256)
k3_head(const float* __restrict__ W_head,
        const float* __restrict__ b_head,
        float* __restrict__ out) {
    const int b    = blockIdx.x;
    const int tid  = threadIdx.x;
    const int warp = tid >> 5;
    const int lane = tid & 31;

    __shared__ __align__(16) float s_t[LSEQ];

    // independent combine loads first (8 L2-hot LDG.128 in flight)
    const float4* gp = reinterpret_cast<const float4*>(&g_partial[b][0][0]);
    float4 v[NE];
    #pragma unroll
    for (int e = 0; e < NE; e++) v[e] = gp[e * 256 + tid];

    // stats recompute (uniform-address, warp-broadcast loads) overlaps above
    float ts = 0.f, tq = 0.f;
    #pragma unroll
    for (int s = 0; s < 8; s++) { ts += g_red[b][s][0]; tq += g_red[b][s][1]; }
    const float mean = ts * (1.0f / LSEQ);
    const float sd   = sqrtf(tq * (1.0f / LSEQ) - mean * mean + 1e-5f);

    float4 acc = v[0];
    #pragma unroll
    for (int e = 1; e < NE; e++) {
        acc.x += v[e].x; acc.y += v[e].y; acc.z += v[e].z; acc.w += v[e].w;
    }
    reinterpret_cast<float4*>(s_t)[tid] =
        make_float4(fmaf(acc.x, sd, mean), fmaf(acc.y, sd, mean),
                    fmaf(acc.z, sd, mean), fmaf(acc.w, sd, mean));
    __syncthreads();

    const int t = blockIdx.y * 8 + warp;
    const float4* wr = reinterpret_cast<const float4*>(W_head + (size_t)t * LSEQ);
    const float4* tt = reinterpret_cast<const float4*>(s_t);
    float ax = 0.f, ay = 0.f, az = 0.f, aw = 0.f;
    #pragma unroll
    for (int q = 0; q < 8; q++) {
        const int i = q * 32 + lane;
        const float4 w = wr[i];
        const float4 f = tt[i];
        ax = fmaf(w.x, f.x, ax);
        ay = fmaf(w.y, f.y, ay);
        az = fmaf(w.z, f.z, az);
        aw = fmaf(w.w, f.w, aw);
    }
    float r = (ax + ay) + (az + aw);
    #pragma unroll
    for (int o = 16; o; o >>= 1) r += __shfl_xor_sync(0xffffffffu, r, o);
    if (lane == 0) out[b * PRED + t] = r + b_head[t];
}

// ---------------------------------------------------------------------------
extern "C" void kernel_launch(void* const* d_in, const int* in_sizes, int n_in,
                              void* d_out, int out_size) {
    const float* x         = (const float*)d_in[0];
    const float* W_proj    = (const float*)d_in[4];
    const float* b_proj    = (const float*)d_in[5];
    const float* W_router  = (const float*)d_in[6];
    const float* b_router  = (const float*)d_in[7];
    const float* W_experts = (const float*)d_in[8];
    const float* b_experts = (const float*)d_in[9];
    const float* W_head    = (const float*)d_in[10];
    const float* b_head    = (const float*)d_in[11];
    float* out = (float*)d_out;

    cudaFuncSetAttribute(k2_fused,
                         cudaFuncAttributeMaxDynamicSharedMemorySize,
                         K2_SMEM_BYTES);

    k0_stats<<<NB * 8, 128>>>(x);
    dim3 g2(NE, NB / 8, NP);
    k2_fused<<<g2, 256, K2_SMEM_BYTES>>>(x, W_proj, b_proj, W_router, b_router,
                                         W_experts, b_experts);
    dim3 g3(NB, PRED / 8);
    k3_head<<<g3, 256>>>(W_head, b_head, out);
}

// round 13
// speedup vs baseline: 1.4009x; 1.4009x over previous
#include <cuda_runtime.h>
#include <math.h>

#define NB    32     // batch
#define LSEQ  1024
#define CH    34
#define D     256
#define NE    8
#define NP    4      // only first 4 patches survive the [:, :seq_len] slice
#define PL    16
#define PRED  96
#define NSEG  4      // stats segments (256 timesteps each)

// Scratch (device globals — no allocation allowed). 16B-aligned for float4 IO.
__device__ float g_red[NB][NSEG][2];          // per-segment partial sums
__device__ float g_sink[4];                   // dead store target (never read)
__device__ __align__(16) float g_xp[NB][NP][D];
__device__ __align__(16) float g_gates[NB][NP][NE];
__device__ __align__(16) float g_partial[NB][NE][NP * D];

// ---------------------------------------------------------------------------
// K0: COALESCED partial stats over x[b,:,2] + L2 warm of W_experts / W_head.
// grid = 128 blocks (b*4 + seg), 256 threads.
// Block reads its 256-timestep chunk of x fully contiguously (all 34 chans,
// 2176 float4) and extracts channel 2 in registers -> streaming bandwidth
// instead of 136B-stride latency-bound loads.
// ---------------------------------------------------------------------------
__global__ void __launch_bounds__(256)
k0_stats(const float* __restrict__ x,
         const float* __restrict__ W_experts,
         const float* __restrict__ W_head) {
    const int blk = blockIdx.x;
    const int b   = blk >> 2;
    const int seg = blk & 3;
    const int tid  = threadIdx.x;
    const int warp = tid >> 5;
    const int lane = tid & 31;

    __shared__ float sred[16];

    // L2 warm (independent coalesced loads; overlap with x streaming)
    float wacc = 0.f;
    {
        const float4* we4 = reinterpret_cast<const float4*>(W_experts);
        #pragma unroll
        for (int i = 0; i < 4; i++) {
            const float4 t = we4[(size_t)blk * 1024 + i * 256 + tid];
            wacc += t.x + t.y + t.z + t.w;
        }
        if (tid < 192) {
            const float4 t = reinterpret_cast<const float4*>(W_head)[(size_t)blk * 192 + tid];
            wacc += t.x + t.y + t.z + t.w;
        }
    }

    // coalesced x chunk: floats [base, base+8704), base divisible by 34
    const float4* xs = reinterpret_cast<const float4*>(
        x + ((size_t)b * LSEQ + seg * 256) * CH);
    float sum = 0.f, sq = 0.f;
    #pragma unroll
    for (int it = 0; it < 9; it++) {
        const int i = tid + it * 256;
        if (it < 8 || i < 2176) {
            const float4 v = xs[i];
            const int f = i * 4;
            #pragma unroll
            for (int j = 0; j < 4; j++) {
                const float el = (j == 0) ? v.x : (j == 1) ? v.y : (j == 2) ? v.z : v.w;
                if ((f + j) % CH == 2) { sum += el; sq += el * el; }
            }
        }
    }

    #pragma unroll
    for (int o = 16; o; o >>= 1) {
        sum += __shfl_xor_sync(0xffffffffu, sum, o);
        sq  += __shfl_xor_sync(0xffffffffu, sq,  o);
    }
    if (lane == 0) { sred[warp] = sum; sred[8 + warp] = sq; }
    __syncthreads();
    if (tid == 0) {
        float ts = 0.f, tq = 0.f;
        #pragma unroll
        for (int w = 0; w < 8; w++) { ts += sred[w]; tq += sred[8 + w]; }
        g_red[b][seg][0] = ts;
        g_red[b][seg][1] = tq;
    }
    // keep warm loads alive; never fires on finite inputs (deterministic)
    if (wacc != wacc) g_sink[0] = wacc;
}

// ---------------------------------------------------------------------------
// K1: finalize stats + patch projection + router gates. grid=32, 256 thr.
// ---------------------------------------------------------------------------
__global__ void __launch_bounds__(256)
k1_prep(const float* __restrict__ x,
        const float* __restrict__ W_proj,
        const float* __restrict__ b_proj,
        const float* __restrict__ W_router,
        const float* __restrict__ b_router) {
    const int b    = blockIdx.x;
    const int tid  = threadIdx.x;
    const int warp = tid >> 5;
    const int lane = tid & 31;

    __shared__ __align__(16) float s_xn[NP * PL];
    __shared__ __align__(16) float s_xp[NP * D];
    __shared__ float s_logit[NP * NE];
    __shared__ float s_mean, s_inv;

    // early independent load: first 64 values of x[b,:,2]
    float v = 0.f;
    if (tid < NP * PL)
        v = x[(size_t)b * LSEQ * CH + (size_t)tid * CH + 2];

    if (tid == 0) {
        float ts = 0.f, tq = 0.f;
        #pragma unroll
        for (int s = 0; s < NSEG; s++) { ts += g_red[b][s][0]; tq += g_red[b][s][1]; }
        const float mean = ts * (1.0f / LSEQ);
        const float var  = tq * (1.0f / LSEQ) - mean * mean;
        const float sd   = sqrtf(var + 1e-5f);
        s_mean = mean; s_inv = 1.0f / sd;
    }
    __syncthreads();

    if (tid < NP * PL) s_xn[tid] = (v - s_mean) * s_inv;
    __syncthreads();

    // ---- xp[p][d], d = tid ----
    {
        const float4* wr4 = reinterpret_cast<const float4*>(W_proj + tid * PL);
        float w[PL];
        #pragma unroll
        for (int q = 0; q < 4; q++) {
            const float4 t = wr4[q];
            w[q * 4 + 0] = t.x; w[q * 4 + 1] = t.y; w[q * 4 + 2] = t.z; w[q * 4 + 3] = t.w;
        }
        const float bp = b_proj[tid];
        #pragma unroll
        for (int p = 0; p < NP; p++) {
            float acc = bp;
            #pragma unroll
            for (int k = 0; k < PL; k++) acc = fmaf(w[k], s_xn[p * PL + k], acc);
            s_xp[p * D + tid] = acc;
        }
    }
    __syncthreads();

    // publish xp (float4)
    reinterpret_cast<float4*>(&g_xp[b][0][0])[tid] =
        reinterpret_cast<const float4*>(s_xp)[tid & 255];

    // ---- router logits: 8 warps x 4 pi each ----
    #pragma unroll
    for (int r = 0; r < 4; r++) {
        const int pi = warp * 4 + r;            // pi = p*8 + e
        const int p  = pi >> 3, e = pi & 7;
        const float* wr = W_router + e * D;
        float acc = 0.f;
        #pragma unroll
        for (int q = 0; q < D / 32; q++) {
            const int d = lane + q * 32;
            acc = fmaf(wr[d], s_xp[p * D + d], acc);
        }
        #pragma unroll
        for (int o = 16; o; o >>= 1) acc += __shfl_xor_sync(0xffffffffu, acc, o);
        if (lane == 0) s_logit[pi] = acc + b_router[e];
    }
    __syncthreads();

    if (tid < NP) {
        const int p = tid;
        float m = s_logit[p * NE];
        #pragma unroll
        for (int j = 1; j < NE; j++) m = fmaxf(m, s_logit[p * NE + j]);
        float denom = 0.f;
        float ex[NE];
        #pragma unroll
        for (int j = 0; j < NE; j++) { ex[j] = __expf(s_logit[p * NE + j] - m); denom += ex[j]; }
        const float inv = 1.0f / denom;
        #pragma unroll
        for (int j = 0; j < NE; j++) g_gates[b][p][j] = ex[j] * inv;
    }
}

// ---------------------------------------------------------------------------
// K2: per-expert smem GEMM.  grid = (8 e, 4 b-tiles, 4 h-tiles), 256 threads.
// (round-8 proven version: plain fmaf, float4 LDS)
// ---------------------------------------------------------------------------
#define K2_SMEM_BYTES ((64 * 65 + 32 * 65) * 16 + 32 * 4 + 64 * 4)

__global__ void __launch_bounds__(256)
k2_experts(const float* __restrict__ W_experts,
           const float* __restrict__ b_experts) {
    extern __shared__ float4 smem4[];
    float4* s_w  = smem4;                       // 64 rows x 65 float4
    float4* s_xp = smem4 + 64 * 65;             // 32 rows x 65 float4
    float*  s_g  = (float*)(smem4 + 96 * 65);   // 32 gates
    float*  s_be = s_g + 32;                    // 64 biases

    const int e   = blockIdx.x;
    const int bt  = blockIdx.y;
    const int htb = blockIdx.z;
    const int tid = threadIdx.x;

    const float4* Wg = reinterpret_cast<const float4*>(W_experts);
    #pragma unroll
    for (int r = 0; r < 16; r++) {
        const int flat = r * 256 + tid;
        const int row = flat >> 6, col = flat & 63;
        s_w[row * 65 + col] = Wg[(size_t)(e * D + htb * 64 + row) * 64 + col];
    }
    const float4* Xg = reinterpret_cast<const float4*>(g_xp);
    #pragma unroll
    for (int r = 0; r < 8; r++) {
        const int flat = r * 256 + tid;
        const int row = flat >> 6, col = flat & 63;
        s_xp[row * 65 + col] = Xg[(bt * 8 * NP + row) * 64 + col];
    }
    if (tid < 32) {
        const int bl = tid >> 2, p = tid & 3;
        s_g[tid] = g_gates[bt * 8 + bl][p][e];
    }
    if (tid < 64) s_be[tid] = b_experts[e * D + htb * 64 + tid];
    __syncthreads();

    const int kh = tid & 1;
    const int ht = (tid >> 1) & 15;
    const int rt = tid >> 5;

    float acc[4][4];
    #pragma unroll
    for (int i = 0; i < 4; i++)
        #pragma unroll
        for (int j = 0; j < 4; j++) acc[i][j] = 0.f;

    const float4* xb4 = s_xp + rt * 4 * 65 + kh * 32;
    const float4* wb4 = s_w  + ht * 65     + kh * 32;

    #pragma unroll 4
    for (int kk = 0; kk < 32; kk++) {
        const float4 x0 = xb4[0 * 65 + kk];
        const float4 x1 = xb4[1 * 65 + kk];
        const float4 x2 = xb4[2 * 65 + kk];
        const float4 x3 = xb4[3 * 65 + kk];
        const float4 w0 = wb4[0 * 1040 + kk];
        const float4 w1 = wb4[1 * 1040 + kk];
        const float4 w2 = wb4[2 * 1040 + kk];
        const float4 w3 = wb4[3 * 1040 + kk];
        #pragma unroll
        for (int i = 0; i < 4; i++) {
            const float4 xv = (i == 0) ? x0 : (i == 1) ? x1 : (i == 2) ? x2 : x3;
            acc[i][0] = fmaf(xv.x, w0.x, acc[i][0]); acc[i][0] = fmaf(xv.y, w0.y, acc[i][0]);
            acc[i][0] = fmaf(xv.z, w0.z, acc[i][0]); acc[i][0] = fmaf(xv.w, w0.w, acc[i][0]);
            acc[i][1] = fmaf(xv.x, w1.x, acc[i][1]); acc[i][1] = fmaf(xv.y, w1.y, acc[i][1]);
            acc[i][1] = fmaf(xv.z, w1.z, acc[i][1]); acc[i][1] = fmaf(xv.w, w1.w, acc[i][1]);
            acc[i][2] = fmaf(xv.x, w2.x, acc[i][2]); acc[i][2] = fmaf(xv.y, w2.y, acc[i][2]);
            acc[i][2] = fmaf(xv.z, w2.z, acc[i][2]); acc[i][2] = fmaf(xv.w, w2.w, acc[i][2]);
            acc[i][3] = fmaf(xv.x, w3.x, acc[i][3]); acc[i][3] = fmaf(xv.y, w3.y, acc[i][3]);
            acc[i][3] = fmaf(xv.z, w3.z, acc[i][3]); acc[i][3] = fmaf(xv.w, w3.w, acc[i][3]);
        }
    }

    #pragma unroll
    for (int i = 0; i < 4; i++)
        #pragma unroll
        for (int j = 0; j < 4; j++)
            acc[i][j] += __shfl_xor_sync(0xffffffffu, acc[i][j], 1);

    if (kh == 0) {
        #pragma unroll
        for (int i = 0; i < 4; i++) {
            const int r = rt * 4 + i;
            const int b = bt * 8 + (r >> 2);
            const int p = r & 3;
            const float g = s_g[r];
            #pragma unroll
            for (int j = 0; j < 4; j++) {
                const int hl = ht + j * 16;
                g_partial[b][e][p * D + htb * 64 + hl] = g * (acc[i][j] + s_be[hl]);
            }
        }
    }
}

// ---------------------------------------------------------------------------
// K3: combine 8 experts + de-normalize + head matvec.
// grid = (32 b, 12 t-tiles), 256 threads; 8 warps -> 8 outputs per block.
// ---------------------------------------------------------------------------
__global__ void __launch_bounds__(256)
k3_head(const float* __restrict__ W_head,
        const float* __restrict__ b_head,
        float* __restrict__ out) {
    const int b    = blockIdx.x;
    const int tid  = threadIdx.x;
    const int warp = tid >> 5;
    const int lane = tid & 31;

    __shared__ __align__(16) float s_t[LSEQ];

    // independent combine loads first (8 L2-hot LDG.128 in flight)
    const float4* gp = reinterpret_cast<const float4*>(&g_partial[b][0][0]);
    float4 v[NE];
    #pragma unroll
    for (int e = 0; e < NE; e++) v[e] = gp[e * 256 + tid];

    // stats recompute (uniform-address, warp-broadcast loads) overlaps above
    float ts = 0.f, tq = 0.f;
    #pragma unroll
    for (int s = 0; s < NSEG; s++) { ts += g_red[b][s][0]; tq += g_red[b][s][1]; }
    const float mean = ts * (1.0f / LSEQ);
    const float sd   = sqrtf(tq * (1.0f / LSEQ) - mean * mean + 1e-5f);

    float4 acc = v[0];
    #pragma unroll
    for (int e = 1; e < NE; e++) {
        acc.x += v[e].x; acc.y += v[e].y; acc.z += v[e].z; acc.w += v[e].w;
    }
    reinterpret_cast<float4*>(s_t)[tid] =
        make_float4(fmaf(acc.x, sd, mean), fmaf(acc.y, sd, mean),
                    fmaf(acc.z, sd, mean), fmaf(acc.w, sd, mean));
    __syncthreads();

    const int t = blockIdx.y * 8 + warp;
    const float4* wr = reinterpret_cast<const float4*>(W_head + (size_t)t * LSEQ);
    const float4* tt = reinterpret_cast<const float4*>(s_t);
    float ax = 0.f, ay = 0.f, az = 0.f, aw = 0.f;
    #pragma unroll
    for (int q = 0; q < 8; q++) {
        const int i = q * 32 + lane;
        const float4 w = wr[i];
        const float4 f = tt[i];
        ax = fmaf(w.x, f.x, ax);
        ay = fmaf(w.y, f.y, ay);
        az = fmaf(w.z, f.z, az);
        aw = fmaf(w.w, f.w, aw);
    }
    float r = (ax + ay) + (az + aw);
    #pragma unroll
    for (int o = 16; o; o >>= 1) r += __shfl_xor_sync(0xffffffffu, r, o);
    if (lane == 0) out[b * PRED + t] = r + b_head[t];
}

// ---------------------------------------------------------------------------
extern "C" void kernel_launch(void* const* d_in, const int* in_sizes, int n_in,
                              void* d_out, int out_size) {
    const float* x         = (const float*)d_in[0];
    const float* W_proj    = (const float*)d_in[4];
    const float* b_proj    = (const float*)d_in[5];
    const float* W_router  = (const float*)d_in[6];
    const float* b_router  = (const float*)d_in[7];
    const float* W_experts = (const float*)d_in[8];
    const float* b_experts = (const float*)d_in[9];
    const float* W_head    = (const float*)d_in[10];
    const float* b_head    = (const float*)d_in[11];
    float* out = (float*)d_out;

    cudaFuncSetAttribute(k2_experts,
                         cudaFuncAttributeMaxDynamicSharedMemorySize,
                         K2_SMEM_BYTES);

    k0_stats<<<NB * NSEG, 256>>>(x, W_experts, W_head);
    k1_prep<<<NB, 256>>>(x, W_proj, b_proj, W_router, b_router);
    dim3 g2(NE, NB / 8, NP);
    k2_experts<<<g2, 256, K2_SMEM_BYTES>>>(W_experts, b_experts);
    dim3 g3(NB, PRED / 8);
    k3_head<<<g3, 256>>>(W_head, b_head, out);
}